// round 15
// baseline (speedup 1.0000x reference)
#include <cuda_runtime.h>
#include <cuda_bf16.h>
#include <cuda_fp16.h>
#include <cstdint>
#include <math.h>

// LSTM_38646115729591 — 2-layer bidirectional LSTM.
// T=512, B=64, D=512, H=512. Output [T,B,2H] fp32.
// Input GEMMs: mma.sync bf16 3-term split, double-buffered cp.async (r13).
// Recurrence: persistent mma.sync fp16; ROUND-12 simple barrier (fastest).

#define T_LEN 512
#define BATCH 64
#define HID   512
#define G4    2048
#define MROWS (T_LEN * BATCH)   // 32768
#define NBLK  128

// recurrence smem layout (bytes)
#define OFF_W   0                 // 32 rows x 512 fp16 = 32768
#define OFF_H   32768             // 64 rows x 512 fp16 = 65536
#define OFF_PSM 98304             // 3 * 8192 reduction scratch
#define RSMEM_BYTES (98304 + 24576)   // 122880

typedef unsigned long long ull;

// ---- static device scratch ----
__device__ float g_xg_f[(size_t)MROWS * G4];
__device__ float g_xg_b[(size_t)MROWS * G4];
__device__ float g_l0[(size_t)MROWS * 2 * HID];
__device__ __half g_hfp[2][2][BATCH * HID];     // [dir][ping] fp16 h

// barrier state — round-12 layout (simple, unpadded; fastest measured)
__device__ unsigned g_cnt_leaf[2][4];
__device__ unsigned g_cnt_root[2];
__device__ unsigned g_gen[2];

__device__ __nv_bfloat16 g_a_hi[(size_t)MROWS * 1024];
__device__ __nv_bfloat16 g_a_lo[(size_t)MROWS * 1024];
__device__ __nv_bfloat16 g_whi_f[(size_t)G4 * 1024];
__device__ __nv_bfloat16 g_wlo_f[(size_t)G4 * 1024];
__device__ __nv_bfloat16 g_whi_b[(size_t)G4 * 1024];
__device__ __nv_bfloat16 g_wlo_b[(size_t)G4 * 1024];

__device__ __forceinline__ float sigf(float x) { return 1.0f / (1.0f + __expf(-x)); }

// ---- scoped sync primitives ----
__device__ __forceinline__ unsigned atom_add_acqrel(unsigned* p, unsigned v) {
    unsigned old;
    asm volatile("atom.add.acq_rel.gpu.u32 %0, [%1], %2;"
                 : "=r"(old) : "l"(p), "r"(v) : "memory");
    return old;
}
__device__ __forceinline__ unsigned ld_acq(const unsigned* p) {
    unsigned v;
    asm volatile("ld.acquire.gpu.u32 %0, [%1];" : "=r"(v) : "l"(p) : "memory");
    return v;
}
__device__ __forceinline__ void st_rel(unsigned* p, unsigned v) {
    asm volatile("st.release.gpu.u32 [%0], %1;" :: "l"(p), "r"(v) : "memory");
}
__device__ __forceinline__ void st_rlx(unsigned* p, unsigned v) {
    asm volatile("st.relaxed.gpu.u32 [%0], %1;" :: "l"(p), "r"(v) : "memory");
}

// ---- mma.sync / cp.async helpers (sm_80 PTX — valid on compute_103) ----
__device__ __forceinline__ uint32_t s2u(const void* p) {
    return (uint32_t)__cvta_generic_to_shared(p);
}
__device__ __forceinline__ void ldsm4(uint32_t* r, uint32_t addr) {
    asm volatile(
        "ldmatrix.sync.aligned.m8n8.x4.shared.b16 {%0,%1,%2,%3}, [%4];"
        : "=r"(r[0]), "=r"(r[1]), "=r"(r[2]), "=r"(r[3]) : "r"(addr));
}
__device__ __forceinline__ void mma_bf16(float* d, const uint32_t* a,
                                         const uint32_t* b) {
    asm volatile(
        "mma.sync.aligned.m16n8k16.row.col.f32.bf16.bf16.f32 "
        "{%0,%1,%2,%3}, {%4,%5,%6,%7}, {%8,%9}, {%0,%1,%2,%3};"
        : "+f"(d[0]), "+f"(d[1]), "+f"(d[2]), "+f"(d[3])
        : "r"(a[0]), "r"(a[1]), "r"(a[2]), "r"(a[3]), "r"(b[0]), "r"(b[1]));
}
__device__ __forceinline__ void mma_f16(float* d, const uint32_t* a,
                                        const uint32_t* b) {
    asm volatile(
        "mma.sync.aligned.m16n8k16.row.col.f32.f16.f16.f32 "
        "{%0,%1,%2,%3}, {%4,%5,%6,%7}, {%8,%9}, {%0,%1,%2,%3};"
        : "+f"(d[0]), "+f"(d[1]), "+f"(d[2]), "+f"(d[3])
        : "r"(a[0]), "r"(a[1]), "r"(a[2]), "r"(a[3]), "r"(b[0]), "r"(b[1]));
}
__device__ __forceinline__ void cpa16(uint32_t smem_dst, const void* gsrc) {
    asm volatile("cp.async.cg.shared.global [%0], [%1], 16;"
                 :: "r"(smem_dst), "l"(__cvta_generic_to_global(gsrc))
                 : "memory");
}
__device__ __forceinline__ void cpa_commit() {
    asm volatile("cp.async.commit_group;" ::: "memory");
}
template <int N>
__device__ __forceinline__ void cpa_wait() {
    asm volatile("cp.async.wait_group %0;" :: "n"(N) : "memory");
}
// split two floats into packed bf16 hi-pair and lo-pair (residual)
__device__ __forceinline__ void split2(float a, float b,
                                       unsigned& h, unsigned& l) {
    const __nv_bfloat16 ha = __float2bfloat16_rn(a);
    const __nv_bfloat16 hb = __float2bfloat16_rn(b);
    const float ra = a - __bfloat162float(ha);
    const float rb = b - __bfloat162float(hb);
    h = (unsigned)__bfloat16_as_ushort(ha)
      | ((unsigned)__bfloat16_as_ushort(hb) << 16);
    l = (unsigned)__bfloat16_as_ushort(__float2bfloat16_rn(ra))
      | ((unsigned)__bfloat16_as_ushort(__float2bfloat16_rn(rb)) << 16);
}
__device__ __forceinline__ unsigned packh2(float a, float b) {
    const __half2 h2 = __floats2half2_rn(a, b);
    return *(const unsigned*)&h2;
}

// =====================================================================
// split_bf16: v -> hi = bf16(v), lo = bf16(v - hi)
// =====================================================================
__global__ void split_bf16(const float* __restrict__ src,
                           __nv_bfloat16* __restrict__ hi,
                           __nv_bfloat16* __restrict__ lo,
                           size_t n)
{
    size_t i = (size_t)blockIdx.x * blockDim.x + threadIdx.x;
    const size_t stride = (size_t)gridDim.x * blockDim.x;
    for (; i < n; i += stride) {
        const float v = src[i];
        const __nv_bfloat16 h = __float2bfloat16_rn(v);
        const float r = v - __bfloat162float(h);
        hi[i] = h;
        lo[i] = __float2bfloat16_rn(r);
    }
}

// =====================================================================
// gemm_mma: 3-term bf16 split GEMM, 2-stage cp.async double buffering.
// (round-13 version — tensor 71.9%, kept)
// =====================================================================
__global__ __launch_bounds__(256, 2)
void gemm_mma(const __nv_bfloat16* __restrict__ Ahi,
              const __nv_bfloat16* __restrict__ Alo,
              const __nv_bfloat16* __restrict__ Whi,
              const __nv_bfloat16* __restrict__ Wlo,
              const float* __restrict__ b1, const float* __restrict__ b2,
              float* __restrict__ C, int K)
{
    __shared__ alignas(128) char sT[2][4][8192];   // [stage][tile]
    __shared__ float bias_sm[128];

    const int tid  = threadIdx.x;
    const int wid  = tid >> 5;
    const int lane = tid & 31;
    const int bm   = blockIdx.y * 128;
    const int bn   = blockIdx.x * 128;
    const int wm   = wid & 1;
    const int wn   = wid >> 1;

    if (tid < 128) bias_sm[tid] = b1[bn + tid] + b2[bn + tid];

    const int q   = lane >> 3;
    const int rA  = (q & 1) * 8 + (lane & 7);
    const int caA = q >> 1;
    const int sa  = (rA >> 1) & 3;
    const int rB  = (q >> 1) * 8 + (lane & 7);
    const int cbB = q & 1;
    const int sb  = (rB >> 1) & 3;

    const uint32_t smem0 = s2u(sT);
    const uint32_t aRowB = (uint32_t)(wm * 64 + rA) * 64;
    const uint32_t bRowB = (uint32_t)(wn * 32 + rB) * 64;
    uint32_t aCk[2], bCk[2];
#pragma unroll
    for (int k = 0; k < 2; k++) {
        aCk[k] = (uint32_t)((((k << 1) + caA) ^ sa) * 16);
        bCk[k] = (uint32_t)((((k << 1) + cbB) ^ sb) * 16);
    }

    const int lrow = tid >> 2;
    const int lch  = tid & 3;
    uint32_t stOff[2];
#pragma unroll
    for (int r = 0; r < 2; r++) {
        const int row = lrow + r * 64;
        stOff[r] = (uint32_t)(row * 64 + ((lch ^ ((row >> 1) & 3)) * 16));
    }
    const __nv_bfloat16* src[4][2];
#pragma unroll
    for (int r = 0; r < 2; r++) {
        src[0][r] = Ahi + (size_t)(bm + lrow + 64 * r) * K + lch * 8;
        src[1][r] = Alo + (size_t)(bm + lrow + 64 * r) * K + lch * 8;
        src[2][r] = Whi + (size_t)(bn + lrow + 64 * r) * K + lch * 8;
        src[3][r] = Wlo + (size_t)(bn + lrow + 64 * r) * K + lch * 8;
    }

    float acc[4][4][4];
#pragma unroll
    for (int i = 0; i < 4; i++)
#pragma unroll
        for (int j = 0; j < 4; j++)
#pragma unroll
            for (int e = 0; e < 4; e++) acc[i][j][e] = 0.0f;

    const int nslab = K / 32;

    // prologue: stage 0
#pragma unroll
    for (int t = 0; t < 4; t++)
#pragma unroll
        for (int r = 0; r < 2; r++)
            cpa16(s2u(sT[0][t]) + stOff[r], src[t][r]);
    cpa_commit();

    for (int s = 0; s < nslab; s++) {
        const int cur = s & 1;
        if (s + 1 < nslab) {
#pragma unroll
            for (int t = 0; t < 4; t++)
#pragma unroll
                for (int r = 0; r < 2; r++)
                    cpa16(s2u(sT[cur ^ 1][t]) + stOff[r],
                          src[t][r] + (s + 1) * 32);
            cpa_commit();
            cpa_wait<1>();
        } else {
            cpa_wait<0>();
        }
        __syncthreads();

        const uint32_t base = smem0 + (uint32_t)cur * 32768u;
#pragma unroll
        for (int kx = 0; kx < 2; kx++) {
            uint32_t ah[16], wh[8], wl[8], al[16];
#pragma unroll
            for (int fm = 0; fm < 4; fm++)
                ldsm4(&ah[fm * 4], base + 0 * 8192 + aRowB + fm * 1024 + aCk[kx]);
#pragma unroll
            for (int fp = 0; fp < 2; fp++)
                ldsm4(&wh[fp * 4], base + 2 * 8192 + bRowB + fp * 1024 + bCk[kx]);
#pragma unroll
            for (int fm = 0; fm < 4; fm++)
#pragma unroll
                for (int fn = 0; fn < 4; fn++)
                    mma_bf16(acc[fm][fn], &ah[fm * 4], &wh[fn * 2]);
#pragma unroll
            for (int fp = 0; fp < 2; fp++)
                ldsm4(&wl[fp * 4], base + 3 * 8192 + bRowB + fp * 1024 + bCk[kx]);
#pragma unroll
            for (int fm = 0; fm < 4; fm++)
#pragma unroll
                for (int fn = 0; fn < 4; fn++)
                    mma_bf16(acc[fm][fn], &ah[fm * 4], &wl[fn * 2]);
#pragma unroll
            for (int fm = 0; fm < 4; fm++)
                ldsm4(&al[fm * 4], base + 1 * 8192 + aRowB + fm * 1024 + aCk[kx]);
#pragma unroll
            for (int fm = 0; fm < 4; fm++)
#pragma unroll
                for (int fn = 0; fn < 4; fn++)
                    mma_bf16(acc[fm][fn], &al[fm * 4], &wh[fn * 2]);
        }
        __syncthreads();   // stage reuse guard
    }

#pragma unroll
    for (int fm = 0; fm < 4; fm++) {
        const int m0 = bm + wm * 64 + fm * 16 + (lane >> 2);
#pragma unroll
        for (int fn = 0; fn < 4; fn++) {
            const int c0 = wn * 32 + fn * 8 + (lane & 3) * 2;
            float2 v0, v1;
            v0.x = acc[fm][fn][0] + bias_sm[c0];
            v0.y = acc[fm][fn][1] + bias_sm[c0 + 1];
            v1.x = acc[fm][fn][2] + bias_sm[c0];
            v1.y = acc[fm][fn][3] + bias_sm[c0 + 1];
            *(float2*)&C[(size_t)m0 * G4 + bn + c0] = v0;
            *(float2*)&C[(size_t)(m0 + 8) * G4 + bn + c0] = v1;
        }
    }
}

// =====================================================================
// init_state: zero fp16 h ping-pong planes + barrier state
// =====================================================================
__global__ void init_state()
{
    const int i = blockIdx.x * blockDim.x + threadIdx.x;   // 65536 threads
    unsigned* p = (unsigned*)g_hfp;                        // 65536 words
    p[i] = 0u;
    if (i < 4) { g_cnt_leaf[0][i] = 0u; g_cnt_leaf[1][i] = 0u; }
    if (i < 2) { g_cnt_root[i] = 0u; g_gen[i] = 0u; }
}

// =====================================================================
// Per-direction tree barrier — EXACT round-12 version (fastest measured)
// =====================================================================
__device__ __forceinline__ void dir_barrier(int dir, int bx)
{
    __syncthreads();
    if (threadIdx.x == 0) {
        unsigned* gen_p = &g_gen[dir];
        const unsigned gen = ld_acq(gen_p);
        const int g = (bx & 63) >> 4;
        if (atom_add_acqrel(&g_cnt_leaf[dir][g], 1u) == 15u) {
            st_rlx(&g_cnt_leaf[dir][g], 0u);
            if (atom_add_acqrel(&g_cnt_root[dir], 1u) == 3u) {
                st_rlx(&g_cnt_root[dir], 0u);
                st_rel(gen_p, gen + 1u);
            } else {
                while (ld_acq(gen_p) == gen) { }
            }
        } else {
            while (ld_acq(gen_p) == gen) { }
        }
    }
    __syncthreads();
}

// =====================================================================
// Persistent recurrence via fp16 mma.sync (round-12 passing structure)
// =====================================================================
__global__ __launch_bounds__(512) void lstm_persist_mma(
    const float* __restrict__ xg_f, const float* __restrict__ xg_b,
    const float* __restrict__ whh_f, const float* __restrict__ whh_b,
    float* __restrict__ out,
    __nv_bfloat16* __restrict__ aH, __nv_bfloat16* __restrict__ aL)
{
    extern __shared__ char smc[];
    const uint32_t smem_u = s2u(smc);
    float* psm = (float*)(smc + OFF_PSM);

    const int tid  = threadIdx.x;
    const int bx   = blockIdx.x;
    const int dir  = bx >> 6;
    const int hb   = bx & 63;
    const int u0   = hb * 8;
    const int w    = tid >> 5;
    const int lane = tid & 31;
    const int wm   = w & 3;
    const int kq   = w >> 2;                               // 0..3
    const int q    = lane >> 3;
    const int l7   = lane & 7;

    const float* xg  = dir ? xg_b : xg_f;
    const float* whh = dir ? whh_b : whh_f;

    // ---- one-time: W slice (32 rows x 512) -> smem fp16, swizzled ----
    for (int ci = tid; ci < 32 * 64; ci += 512) {          // 16B chunks
        const int row = ci >> 6, c = ci & 63;
        const int grow = (row >> 3) * HID + u0 + (row & 7);
        const float4 f0 = __ldg((const float4*)&whh[(size_t)grow * HID + c * 8]);
        const float4 f1 = __ldg((const float4*)&whh[(size_t)grow * HID + c * 8 + 4]);
        const uint4 v = make_uint4(packh2(f0.x, f0.y), packh2(f0.z, f0.w),
                                   packh2(f1.x, f1.y), packh2(f1.z, f1.w));
        const uint32_t dst = (uint32_t)(row * 1024 + ((c ^ (row & 7)) << 4));
        *(uint4*)(smc + OFF_W + dst) = v;
    }
    __syncthreads();

    // ldmatrix lane geometry
    const int aRow = wm * 16 + (q & 1) * 8 + l7;           // A rows (batch)
    const int aSel = q >> 1;
    const int aXor = aRow & 7;
    const uint32_t aBase = (uint32_t)aRow * 1024;
    const int bRow = (q >> 1) * 8 + l7;                    // B rows (gates)
    const int bSel = q & 1;
    const int bXor = bRow & 7;
    const uint32_t bBase0 = (uint32_t)bRow * 1024;
    const uint32_t bBase1 = (uint32_t)(bRow + 16) * 1024;

    const int m0 = wm * 16 + (lane >> 2);                  // epilogue cells
    const int j2 = (lane & 3) * 2;
    const int uu2 = u0 + j2;

    float cst[2][2] = {{0.0f, 0.0f}, {0.0f, 0.0f}};        // c-state (kq==0)
    const int kb8 = kq * 8;

    for (int t = 0; t < T_LEN; t++) {
        const int t_eff = dir ? (T_LEN - 1 - t) : t;
        const int ping  = t & 1;
        const __half* hp = &g_hfp[dir][ping][0];
        __half*       hn = &g_hfp[dir][ping ^ 1][0];

        // ---- stage h plane (64 x 512 fp16) via cp.async ----
#pragma unroll
        for (int it = 0; it < 8; it++) {
            const int ci = tid + it * 512;                 // 0..4095
            const int row = ci >> 6, c = ci & 63;
            const uint32_t dst = (uint32_t)(row * 1024 + ((c ^ (row & 7)) << 4));
            cpa16(smem_u + OFF_H + dst, hp + row * 512 + c * 8);
        }

        // prefetch xg gate rows while cp.async is in flight
        float2 xr[4][2];
        if (kq == 0) {
#pragma unroll
            for (int g = 0; g < 4; g++)
#pragma unroll
                for (int r = 0; r < 2; r++) {
                    const int b = m0 + r * 8;
                    xr[g][r] = __ldg((const float2*)
                        &xg[((size_t)t_eff * BATCH + b) * G4 + g * HID + uu2]);
                }
        }

        cpa_commit();
        cpa_wait<0>();
        __syncthreads();

        // ---- mma over this warp's K-quarter: 8 k16 steps ----
        float acc[4][4];
#pragma unroll
        for (int fn = 0; fn < 4; fn++)
#pragma unroll
            for (int e = 0; e < 4; e++) acc[fn][e] = 0.0f;

#pragma unroll
        for (int kk = 0; kk < 8; kk++) {
            const int s = kb8 + kk;
            const uint32_t ca = (uint32_t)(((2 * s + aSel) ^ aXor) << 4);
            const uint32_t cb = (uint32_t)(((2 * s + bSel) ^ bXor) << 4);
            uint32_t a[4], w0[4], w1[4];
            ldsm4(a,  smem_u + OFF_H + aBase + ca);
            ldsm4(w0, smem_u + OFF_W + bBase0 + cb);
            ldsm4(w1, smem_u + OFF_W + bBase1 + cb);
            mma_f16(acc[0], a, w0 + 0);
            mma_f16(acc[1], a, w0 + 2);
            mma_f16(acc[2], a, w1 + 0);
            mma_f16(acc[3], a, w1 + 2);
        }

        // ---- K-quarter reduction (kq 1..3 -> psm; kq 0 finalizes) ----
        if (kq != 0) {
            float* pp = psm + ((kq - 1) * 128 + wm * 32 + lane) * 16;
#pragma unroll
            for (int fn = 0; fn < 4; fn++)
#pragma unroll
                for (int e = 0; e < 4; e++) pp[fn * 4 + e] = acc[fn][e];
        }
        __syncthreads();

        if (kq == 0) {
#pragma unroll
            for (int kqq = 0; kqq < 3; kqq++) {
                const float* pp = psm + (kqq * 128 + wm * 32 + lane) * 16;
#pragma unroll
                for (int fn = 0; fn < 4; fn++)
#pragma unroll
                    for (int e = 0; e < 4; e++) acc[fn][e] += pp[fn * 4 + e];
            }

#pragma unroll
            for (int r = 0; r < 2; r++) {
                const int b = m0 + r * 8;
                float hv[2];
#pragma unroll
                for (int cc = 0; cc < 2; cc++) {
                    const int e = r * 2 + cc;
                    const float gi = acc[0][e] + (cc ? xr[0][r].y : xr[0][r].x);
                    const float gf = acc[1][e] + (cc ? xr[1][r].y : xr[1][r].x);
                    const float gg = acc[2][e] + (cc ? xr[2][r].y : xr[2][r].x);
                    const float go = acc[3][e] + (cc ? xr[3][r].y : xr[3][r].x);
                    cst[r][cc] = sigf(gf) * cst[r][cc] + sigf(gi) * tanhf(gg);
                    hv[cc] = sigf(go) * tanhf(cst[r][cc]);
                }
                __stcg((unsigned*)(hn + b * 512 + uu2), packh2(hv[0], hv[1]));
                if (aH) {
                    // fused next-layer GEMM operand: A[t*64+b, dir*512+u]
                    unsigned ph, pl;
                    split2(hv[0], hv[1], ph, pl);
                    const size_t arow = ((size_t)t_eff * BATCH + b) * 1024
                                        + dir * HID + uu2;
                    __stcg((unsigned*)(aH + arow), ph);
                    __stcg((unsigned*)(aL + arow), pl);
                } else {
                    *(float2*)&out[((size_t)t_eff * BATCH + b) * (2 * HID)
                                   + dir * HID + uu2] = make_float2(hv[0], hv[1]);
                }
            }
        }

        dir_barrier(dir, bx);
    }
}

// =====================================================================
// host
// =====================================================================
extern "C" void kernel_launch(void* const* d_in, const int* in_sizes, int n_in,
                              void* d_out, int out_size)
{
    const float* x       = (const float*)d_in[0];
    const float* w_ih0_f = (const float*)d_in[1];
    const float* w_hh0_f = (const float*)d_in[2];
    const float* b_ih0_f = (const float*)d_in[3];
    const float* b_hh0_f = (const float*)d_in[4];
    const float* w_ih0_b = (const float*)d_in[5];
    const float* w_hh0_b = (const float*)d_in[6];
    const float* b_ih0_b = (const float*)d_in[7];
    const float* b_hh0_b = (const float*)d_in[8];
    const float* w_ih1_f = (const float*)d_in[9];
    const float* w_hh1_f = (const float*)d_in[10];
    const float* b_ih1_f = (const float*)d_in[11];
    const float* b_hh1_f = (const float*)d_in[12];
    const float* w_ih1_b = (const float*)d_in[13];
    const float* w_hh1_b = (const float*)d_in[14];
    const float* b_ih1_b = (const float*)d_in[15];
    const float* b_hh1_b = (const float*)d_in[16];
    float* out = (float*)d_out;

    float *xg_f, *xg_b, *l0;
    __nv_bfloat16 *a_hi, *a_lo, *whi_f, *wlo_f, *whi_b, *wlo_b;
    cudaGetSymbolAddress((void**)&xg_f,  g_xg_f);
    cudaGetSymbolAddress((void**)&xg_b,  g_xg_b);
    cudaGetSymbolAddress((void**)&l0,    g_l0);
    cudaGetSymbolAddress((void**)&a_hi,  g_a_hi);
    cudaGetSymbolAddress((void**)&a_lo,  g_a_lo);
    cudaGetSymbolAddress((void**)&whi_f, g_whi_f);
    cudaGetSymbolAddress((void**)&wlo_f, g_wlo_f);
    cudaGetSymbolAddress((void**)&whi_b, g_whi_b);
    cudaGetSymbolAddress((void**)&wlo_b, g_wlo_b);

    cudaFuncSetAttribute(lstm_persist_mma,
                         cudaFuncAttributeMaxDynamicSharedMemorySize, RSMEM_BYTES);

    const dim3 gemm_grid(G4 / 128, MROWS / 128);   // (16, 256)

    // ---- layer 0: split + mma GEMMs (K=512) ----
    split_bf16<<<512, 256>>>(x,       a_hi,  a_lo,  (size_t)MROWS * 512);
    split_bf16<<<256, 256>>>(w_ih0_f, whi_f, wlo_f, (size_t)G4 * 512);
    split_bf16<<<256, 256>>>(w_ih0_b, whi_b, wlo_b, (size_t)G4 * 512);
    gemm_mma<<<gemm_grid, 256>>>(a_hi, a_lo, whi_f, wlo_f, b_ih0_f, b_hh0_f, xg_f, 512);
    gemm_mma<<<gemm_grid, 256>>>(a_hi, a_lo, whi_b, wlo_b, b_ih0_b, b_hh0_b, xg_b, 512);
    init_state<<<256, 256>>>();
    // layer-0 recurrence writes a_hi/a_lo (next layer's A operand) directly
    lstm_persist_mma<<<NBLK, 512, RSMEM_BYTES>>>(xg_f, xg_b, w_hh0_f, w_hh0_b,
                                                 l0, a_hi, a_lo);

    // ---- layer 1: weight splits + mma GEMMs (K=1024) ----
    split_bf16<<<256, 256>>>(w_ih1_f, whi_f, wlo_f, (size_t)G4 * 1024);
    split_bf16<<<256, 256>>>(w_ih1_b, whi_b, wlo_b, (size_t)G4 * 1024);
    gemm_mma<<<gemm_grid, 256>>>(a_hi, a_lo, whi_f, wlo_f, b_ih1_f, b_hh1_f, xg_f, 1024);
    gemm_mma<<<gemm_grid, 256>>>(a_hi, a_lo, whi_b, wlo_b, b_ih1_b, b_hh1_b, xg_b, 1024);
    init_state<<<256, 256>>>();
    lstm_persist_mma<<<NBLK, 512, RSMEM_BYTES>>>(xg_f, xg_b, w_hh1_f, w_hh1_b,
                                                 out, nullptr, nullptr);
}

// round 16
// speedup vs baseline: 1.4758x; 1.4758x over previous
#include <cuda_runtime.h>
#include <cuda_bf16.h>
#include <cuda_fp16.h>
#include <cstdint>
#include <math.h>

// LSTM_38646115729591 — 2-layer bidirectional LSTM.
// T=512, B=64, D=512, H=512. Output [T,B,2H] fp32.
// Input GEMMs: mma.sync bf16 3-term split, double-buffered cp.async (r13).
// Recurrence: persistent mma.sync fp16; ROUND-12 simple barrier.
// RE-BENCH of round-15 source: round-15 measurement showed a 1.55x slowdown
// on a byte-identical gemm_mma (475->735us, same tensor%) => clock throttle,
// not code. Resubmitting unchanged for a clean measurement.

#define T_LEN 512
#define BATCH 64
#define HID   512
#define G4    2048
#define MROWS (T_LEN * BATCH)   // 32768
#define NBLK  128

// recurrence smem layout (bytes)
#define OFF_W   0                 // 32 rows x 512 fp16 = 32768
#define OFF_H   32768             // 64 rows x 512 fp16 = 65536
#define OFF_PSM 98304             // 3 * 8192 reduction scratch
#define RSMEM_BYTES (98304 + 24576)   // 122880

typedef unsigned long long ull;

// ---- static device scratch ----
__device__ float g_xg_f[(size_t)MROWS * G4];
__device__ float g_xg_b[(size_t)MROWS * G4];
__device__ float g_l0[(size_t)MROWS * 2 * HID];
__device__ __half g_hfp[2][2][BATCH * HID];     // [dir][ping] fp16 h

// barrier state — round-12 layout (simple, unpadded; fastest measured)
__device__ unsigned g_cnt_leaf[2][4];
__device__ unsigned g_cnt_root[2];
__device__ unsigned g_gen[2];

__device__ __nv_bfloat16 g_a_hi[(size_t)MROWS * 1024];
__device__ __nv_bfloat16 g_a_lo[(size_t)MROWS * 1024];
__device__ __nv_bfloat16 g_whi_f[(size_t)G4 * 1024];
__device__ __nv_bfloat16 g_wlo_f[(size_t)G4 * 1024];
__device__ __nv_bfloat16 g_whi_b[(size_t)G4 * 1024];
__device__ __nv_bfloat16 g_wlo_b[(size_t)G4 * 1024];

__device__ __forceinline__ float sigf(float x) { return 1.0f / (1.0f + __expf(-x)); }

// ---- scoped sync primitives ----
__device__ __forceinline__ unsigned atom_add_acqrel(unsigned* p, unsigned v) {
    unsigned old;
    asm volatile("atom.add.acq_rel.gpu.u32 %0, [%1], %2;"
                 : "=r"(old) : "l"(p), "r"(v) : "memory");
    return old;
}
__device__ __forceinline__ unsigned ld_acq(const unsigned* p) {
    unsigned v;
    asm volatile("ld.acquire.gpu.u32 %0, [%1];" : "=r"(v) : "l"(p) : "memory");
    return v;
}
__device__ __forceinline__ void st_rel(unsigned* p, unsigned v) {
    asm volatile("st.release.gpu.u32 [%0], %1;" :: "l"(p), "r"(v) : "memory");
}
__device__ __forceinline__ void st_rlx(unsigned* p, unsigned v) {
    asm volatile("st.relaxed.gpu.u32 [%0], %1;" :: "l"(p), "r"(v) : "memory");
}

// ---- mma.sync / cp.async helpers (sm_80 PTX — valid on compute_103) ----
__device__ __forceinline__ uint32_t s2u(const void* p) {
    return (uint32_t)__cvta_generic_to_shared(p);
}
__device__ __forceinline__ void ldsm4(uint32_t* r, uint32_t addr) {
    asm volatile(
        "ldmatrix.sync.aligned.m8n8.x4.shared.b16 {%0,%1,%2,%3}, [%4];"
        : "=r"(r[0]), "=r"(r[1]), "=r"(r[2]), "=r"(r[3]) : "r"(addr));
}
__device__ __forceinline__ void mma_bf16(float* d, const uint32_t* a,
                                         const uint32_t* b) {
    asm volatile(
        "mma.sync.aligned.m16n8k16.row.col.f32.bf16.bf16.f32 "
        "{%0,%1,%2,%3}, {%4,%5,%6,%7}, {%8,%9}, {%0,%1,%2,%3};"
        : "+f"(d[0]), "+f"(d[1]), "+f"(d[2]), "+f"(d[3])
        : "r"(a[0]), "r"(a[1]), "r"(a[2]), "r"(a[3]), "r"(b[0]), "r"(b[1]));
}
__device__ __forceinline__ void mma_f16(float* d, const uint32_t* a,
                                        const uint32_t* b) {
    asm volatile(
        "mma.sync.aligned.m16n8k16.row.col.f32.f16.f16.f32 "
        "{%0,%1,%2,%3}, {%4,%5,%6,%7}, {%8,%9}, {%0,%1,%2,%3};"
        : "+f"(d[0]), "+f"(d[1]), "+f"(d[2]), "+f"(d[3])
        : "r"(a[0]), "r"(a[1]), "r"(a[2]), "r"(a[3]), "r"(b[0]), "r"(b[1]));
}
__device__ __forceinline__ void cpa16(uint32_t smem_dst, const void* gsrc) {
    asm volatile("cp.async.cg.shared.global [%0], [%1], 16;"
                 :: "r"(smem_dst), "l"(__cvta_generic_to_global(gsrc))
                 : "memory");
}
__device__ __forceinline__ void cpa_commit() {
    asm volatile("cp.async.commit_group;" ::: "memory");
}
template <int N>
__device__ __forceinline__ void cpa_wait() {
    asm volatile("cp.async.wait_group %0;" :: "n"(N) : "memory");
}
// split two floats into packed bf16 hi-pair and lo-pair (residual)
__device__ __forceinline__ void split2(float a, float b,
                                       unsigned& h, unsigned& l) {
    const __nv_bfloat16 ha = __float2bfloat16_rn(a);
    const __nv_bfloat16 hb = __float2bfloat16_rn(b);
    const float ra = a - __bfloat162float(ha);
    const float rb = b - __bfloat162float(hb);
    h = (unsigned)__bfloat16_as_ushort(ha)
      | ((unsigned)__bfloat16_as_ushort(hb) << 16);
    l = (unsigned)__bfloat16_as_ushort(__float2bfloat16_rn(ra))
      | ((unsigned)__bfloat16_as_ushort(__float2bfloat16_rn(rb)) << 16);
}
__device__ __forceinline__ unsigned packh2(float a, float b) {
    const __half2 h2 = __floats2half2_rn(a, b);
    return *(const unsigned*)&h2;
}

// =====================================================================
// split_bf16: v -> hi = bf16(v), lo = bf16(v - hi)
// =====================================================================
__global__ void split_bf16(const float* __restrict__ src,
                           __nv_bfloat16* __restrict__ hi,
                           __nv_bfloat16* __restrict__ lo,
                           size_t n)
{
    size_t i = (size_t)blockIdx.x * blockDim.x + threadIdx.x;
    const size_t stride = (size_t)gridDim.x * blockDim.x;
    for (; i < n; i += stride) {
        const float v = src[i];
        const __nv_bfloat16 h = __float2bfloat16_rn(v);
        const float r = v - __bfloat162float(h);
        hi[i] = h;
        lo[i] = __float2bfloat16_rn(r);
    }
}

// =====================================================================
// gemm_mma: 3-term bf16 split GEMM, 2-stage cp.async double buffering.
// =====================================================================
__global__ __launch_bounds__(256, 2)
void gemm_mma(const __nv_bfloat16* __restrict__ Ahi,
              const __nv_bfloat16* __restrict__ Alo,
              const __nv_bfloat16* __restrict__ Whi,
              const __nv_bfloat16* __restrict__ Wlo,
              const float* __restrict__ b1, const float* __restrict__ b2,
              float* __restrict__ C, int K)
{
    __shared__ alignas(128) char sT[2][4][8192];   // [stage][tile]
    __shared__ float bias_sm[128];

    const int tid  = threadIdx.x;
    const int wid  = tid >> 5;
    const int lane = tid & 31;
    const int bm   = blockIdx.y * 128;
    const int bn   = blockIdx.x * 128;
    const int wm   = wid & 1;
    const int wn   = wid >> 1;

    if (tid < 128) bias_sm[tid] = b1[bn + tid] + b2[bn + tid];

    const int q   = lane >> 3;
    const int rA  = (q & 1) * 8 + (lane & 7);
    const int caA = q >> 1;
    const int sa  = (rA >> 1) & 3;
    const int rB  = (q >> 1) * 8 + (lane & 7);
    const int cbB = q & 1;
    const int sb  = (rB >> 1) & 3;

    const uint32_t smem0 = s2u(sT);
    const uint32_t aRowB = (uint32_t)(wm * 64 + rA) * 64;
    const uint32_t bRowB = (uint32_t)(wn * 32 + rB) * 64;
    uint32_t aCk[2], bCk[2];
#pragma unroll
    for (int k = 0; k < 2; k++) {
        aCk[k] = (uint32_t)((((k << 1) + caA) ^ sa) * 16);
        bCk[k] = (uint32_t)((((k << 1) + cbB) ^ sb) * 16);
    }

    const int lrow = tid >> 2;
    const int lch  = tid & 3;
    uint32_t stOff[2];
#pragma unroll
    for (int r = 0; r < 2; r++) {
        const int row = lrow + r * 64;
        stOff[r] = (uint32_t)(row * 64 + ((lch ^ ((row >> 1) & 3)) * 16));
    }
    const __nv_bfloat16* src[4][2];
#pragma unroll
    for (int r = 0; r < 2; r++) {
        src[0][r] = Ahi + (size_t)(bm + lrow + 64 * r) * K + lch * 8;
        src[1][r] = Alo + (size_t)(bm + lrow + 64 * r) * K + lch * 8;
        src[2][r] = Whi + (size_t)(bn + lrow + 64 * r) * K + lch * 8;
        src[3][r] = Wlo + (size_t)(bn + lrow + 64 * r) * K + lch * 8;
    }

    float acc[4][4][4];
#pragma unroll
    for (int i = 0; i < 4; i++)
#pragma unroll
        for (int j = 0; j < 4; j++)
#pragma unroll
            for (int e = 0; e < 4; e++) acc[i][j][e] = 0.0f;

    const int nslab = K / 32;

    // prologue: stage 0
#pragma unroll
    for (int t = 0; t < 4; t++)
#pragma unroll
        for (int r = 0; r < 2; r++)
            cpa16(s2u(sT[0][t]) + stOff[r], src[t][r]);
    cpa_commit();

    for (int s = 0; s < nslab; s++) {
        const int cur = s & 1;
        if (s + 1 < nslab) {
#pragma unroll
            for (int t = 0; t < 4; t++)
#pragma unroll
                for (int r = 0; r < 2; r++)
                    cpa16(s2u(sT[cur ^ 1][t]) + stOff[r],
                          src[t][r] + (s + 1) * 32);
            cpa_commit();
            cpa_wait<1>();
        } else {
            cpa_wait<0>();
        }
        __syncthreads();

        const uint32_t base = smem0 + (uint32_t)cur * 32768u;
#pragma unroll
        for (int kx = 0; kx < 2; kx++) {
            uint32_t ah[16], wh[8], wl[8], al[16];
#pragma unroll
            for (int fm = 0; fm < 4; fm++)
                ldsm4(&ah[fm * 4], base + 0 * 8192 + aRowB + fm * 1024 + aCk[kx]);
#pragma unroll
            for (int fp = 0; fp < 2; fp++)
                ldsm4(&wh[fp * 4], base + 2 * 8192 + bRowB + fp * 1024 + bCk[kx]);
#pragma unroll
            for (int fm = 0; fm < 4; fm++)
#pragma unroll
                for (int fn = 0; fn < 4; fn++)
                    mma_bf16(acc[fm][fn], &ah[fm * 4], &wh[fn * 2]);
#pragma unroll
            for (int fp = 0; fp < 2; fp++)
                ldsm4(&wl[fp * 4], base + 3 * 8192 + bRowB + fp * 1024 + bCk[kx]);
#pragma unroll
            for (int fm = 0; fm < 4; fm++)
#pragma unroll
                for (int fn = 0; fn < 4; fn++)
                    mma_bf16(acc[fm][fn], &ah[fm * 4], &wl[fn * 2]);
#pragma unroll
            for (int fm = 0; fm < 4; fm++)
                ldsm4(&al[fm * 4], base + 1 * 8192 + aRowB + fm * 1024 + aCk[kx]);
#pragma unroll
            for (int fm = 0; fm < 4; fm++)
#pragma unroll
                for (int fn = 0; fn < 4; fn++)
                    mma_bf16(acc[fm][fn], &al[fm * 4], &wh[fn * 2]);
        }
        __syncthreads();   // stage reuse guard
    }

#pragma unroll
    for (int fm = 0; fm < 4; fm++) {
        const int m0 = bm + wm * 64 + fm * 16 + (lane >> 2);
#pragma unroll
        for (int fn = 0; fn < 4; fn++) {
            const int c0 = wn * 32 + fn * 8 + (lane & 3) * 2;
            float2 v0, v1;
            v0.x = acc[fm][fn][0] + bias_sm[c0];
            v0.y = acc[fm][fn][1] + bias_sm[c0 + 1];
            v1.x = acc[fm][fn][2] + bias_sm[c0];
            v1.y = acc[fm][fn][3] + bias_sm[c0 + 1];
            *(float2*)&C[(size_t)m0 * G4 + bn + c0] = v0;
            *(float2*)&C[(size_t)(m0 + 8) * G4 + bn + c0] = v1;
        }
    }
}

// =====================================================================
// init_state: zero fp16 h ping-pong planes + barrier state
// =====================================================================
__global__ void init_state()
{
    const int i = blockIdx.x * blockDim.x + threadIdx.x;   // 65536 threads
    unsigned* p = (unsigned*)g_hfp;                        // 65536 words
    p[i] = 0u;
    if (i < 4) { g_cnt_leaf[0][i] = 0u; g_cnt_leaf[1][i] = 0u; }
    if (i < 2) { g_cnt_root[i] = 0u; g_gen[i] = 0u; }
}

// =====================================================================
// Per-direction tree barrier — round-12 version
// =====================================================================
__device__ __forceinline__ void dir_barrier(int dir, int bx)
{
    __syncthreads();
    if (threadIdx.x == 0) {
        unsigned* gen_p = &g_gen[dir];
        const unsigned gen = ld_acq(gen_p);
        const int g = (bx & 63) >> 4;
        if (atom_add_acqrel(&g_cnt_leaf[dir][g], 1u) == 15u) {
            st_rlx(&g_cnt_leaf[dir][g], 0u);
            if (atom_add_acqrel(&g_cnt_root[dir], 1u) == 3u) {
                st_rlx(&g_cnt_root[dir], 0u);
                st_rel(gen_p, gen + 1u);
            } else {
                while (ld_acq(gen_p) == gen) { }
            }
        } else {
            while (ld_acq(gen_p) == gen) { }
        }
    }
    __syncthreads();
}

// =====================================================================
// Persistent recurrence via fp16 mma.sync
// =====================================================================
__global__ __launch_bounds__(512) void lstm_persist_mma(
    const float* __restrict__ xg_f, const float* __restrict__ xg_b,
    const float* __restrict__ whh_f, const float* __restrict__ whh_b,
    float* __restrict__ out,
    __nv_bfloat16* __restrict__ aH, __nv_bfloat16* __restrict__ aL)
{
    extern __shared__ char smc[];
    const uint32_t smem_u = s2u(smc);
    float* psm = (float*)(smc + OFF_PSM);

    const int tid  = threadIdx.x;
    const int bx   = blockIdx.x;
    const int dir  = bx >> 6;
    const int hb   = bx & 63;
    const int u0   = hb * 8;
    const int w    = tid >> 5;
    const int lane = tid & 31;
    const int wm   = w & 3;
    const int kq   = w >> 2;                               // 0..3
    const int q    = lane >> 3;
    const int l7   = lane & 7;

    const float* xg  = dir ? xg_b : xg_f;
    const float* whh = dir ? whh_b : whh_f;

    // ---- one-time: W slice (32 rows x 512) -> smem fp16, swizzled ----
    for (int ci = tid; ci < 32 * 64; ci += 512) {          // 16B chunks
        const int row = ci >> 6, c = ci & 63;
        const int grow = (row >> 3) * HID + u0 + (row & 7);
        const float4 f0 = __ldg((const float4*)&whh[(size_t)grow * HID + c * 8]);
        const float4 f1 = __ldg((const float4*)&whh[(size_t)grow * HID + c * 8 + 4]);
        const uint4 v = make_uint4(packh2(f0.x, f0.y), packh2(f0.z, f0.w),
                                   packh2(f1.x, f1.y), packh2(f1.z, f1.w));
        const uint32_t dst = (uint32_t)(row * 1024 + ((c ^ (row & 7)) << 4));
        *(uint4*)(smc + OFF_W + dst) = v;
    }
    __syncthreads();

    // ldmatrix lane geometry
    const int aRow = wm * 16 + (q & 1) * 8 + l7;           // A rows (batch)
    const int aSel = q >> 1;
    const int aXor = aRow & 7;
    const uint32_t aBase = (uint32_t)aRow * 1024;
    const int bRow = (q >> 1) * 8 + l7;                    // B rows (gates)
    const int bSel = q & 1;
    const int bXor = bRow & 7;
    const uint32_t bBase0 = (uint32_t)bRow * 1024;
    const uint32_t bBase1 = (uint32_t)(bRow + 16) * 1024;

    const int m0 = wm * 16 + (lane >> 2);                  // epilogue cells
    const int j2 = (lane & 3) * 2;
    const int uu2 = u0 + j2;

    float cst[2][2] = {{0.0f, 0.0f}, {0.0f, 0.0f}};        // c-state (kq==0)
    const int kb8 = kq * 8;

    for (int t = 0; t < T_LEN; t++) {
        const int t_eff = dir ? (T_LEN - 1 - t) : t;
        const int ping  = t & 1;
        const __half* hp = &g_hfp[dir][ping][0];
        __half*       hn = &g_hfp[dir][ping ^ 1][0];

        // ---- stage h plane (64 x 512 fp16) via cp.async ----
#pragma unroll
        for (int it = 0; it < 8; it++) {
            const int ci = tid + it * 512;                 // 0..4095
            const int row = ci >> 6, c = ci & 63;
            const uint32_t dst = (uint32_t)(row * 1024 + ((c ^ (row & 7)) << 4));
            cpa16(smem_u + OFF_H + dst, hp + row * 512 + c * 8);
        }

        // prefetch xg gate rows while cp.async is in flight
        float2 xr[4][2];
        if (kq == 0) {
#pragma unroll
            for (int g = 0; g < 4; g++)
#pragma unroll
                for (int r = 0; r < 2; r++) {
                    const int b = m0 + r * 8;
                    xr[g][r] = __ldg((const float2*)
                        &xg[((size_t)t_eff * BATCH + b) * G4 + g * HID + uu2]);
                }
        }

        cpa_commit();
        cpa_wait<0>();
        __syncthreads();

        // ---- mma over this warp's K-quarter: 8 k16 steps ----
        float acc[4][4];
#pragma unroll
        for (int fn = 0; fn < 4; fn++)
#pragma unroll
            for (int e = 0; e < 4; e++) acc[fn][e] = 0.0f;

#pragma unroll
        for (int kk = 0; kk < 8; kk++) {
            const int s = kb8 + kk;
            const uint32_t ca = (uint32_t)(((2 * s + aSel) ^ aXor) << 4);
            const uint32_t cb = (uint32_t)(((2 * s + bSel) ^ bXor) << 4);
            uint32_t a[4], w0[4], w1[4];
            ldsm4(a,  smem_u + OFF_H + aBase + ca);
            ldsm4(w0, smem_u + OFF_W + bBase0 + cb);
            ldsm4(w1, smem_u + OFF_W + bBase1 + cb);
            mma_f16(acc[0], a, w0 + 0);
            mma_f16(acc[1], a, w0 + 2);
            mma_f16(acc[2], a, w1 + 0);
            mma_f16(acc[3], a, w1 + 2);
        }

        // ---- K-quarter reduction (kq 1..3 -> psm; kq 0 finalizes) ----
        if (kq != 0) {
            float* pp = psm + ((kq - 1) * 128 + wm * 32 + lane) * 16;
#pragma unroll
            for (int fn = 0; fn < 4; fn++)
#pragma unroll
                for (int e = 0; e < 4; e++) pp[fn * 4 + e] = acc[fn][e];
        }
        __syncthreads();

        if (kq == 0) {
#pragma unroll
            for (int kqq = 0; kqq < 3; kqq++) {
                const float* pp = psm + (kqq * 128 + wm * 32 + lane) * 16;
#pragma unroll
                for (int fn = 0; fn < 4; fn++)
#pragma unroll
                    for (int e = 0; e < 4; e++) acc[fn][e] += pp[fn * 4 + e];
            }

#pragma unroll
            for (int r = 0; r < 2; r++) {
                const int b = m0 + r * 8;
                float hv[2];
#pragma unroll
                for (int cc = 0; cc < 2; cc++) {
                    const int e = r * 2 + cc;
                    const float gi = acc[0][e] + (cc ? xr[0][r].y : xr[0][r].x);
                    const float gf = acc[1][e] + (cc ? xr[1][r].y : xr[1][r].x);
                    const float gg = acc[2][e] + (cc ? xr[2][r].y : xr[2][r].x);
                    const float go = acc[3][e] + (cc ? xr[3][r].y : xr[3][r].x);
                    cst[r][cc] = sigf(gf) * cst[r][cc] + sigf(gi) * tanhf(gg);
                    hv[cc] = sigf(go) * tanhf(cst[r][cc]);
                }
                __stcg((unsigned*)(hn + b * 512 + uu2), packh2(hv[0], hv[1]));
                if (aH) {
                    // fused next-layer GEMM operand: A[t*64+b, dir*512+u]
                    unsigned ph, pl;
                    split2(hv[0], hv[1], ph, pl);
                    const size_t arow = ((size_t)t_eff * BATCH + b) * 1024
                                        + dir * HID + uu2;
                    __stcg((unsigned*)(aH + arow), ph);
                    __stcg((unsigned*)(aL + arow), pl);
                } else {
                    *(float2*)&out[((size_t)t_eff * BATCH + b) * (2 * HID)
                                   + dir * HID + uu2] = make_float2(hv[0], hv[1]);
                }
            }
        }

        dir_barrier(dir, bx);
    }
}

// =====================================================================
// host
// =====================================================================
extern "C" void kernel_launch(void* const* d_in, const int* in_sizes, int n_in,
                              void* d_out, int out_size)
{
    const float* x       = (const float*)d_in[0];
    const float* w_ih0_f = (const float*)d_in[1];
    const float* w_hh0_f = (const float*)d_in[2];
    const float* b_ih0_f = (const float*)d_in[3];
    const float* b_hh0_f = (const float*)d_in[4];
    const float* w_ih0_b = (const float*)d_in[5];
    const float* w_hh0_b = (const float*)d_in[6];
    const float* b_ih0_b = (const float*)d_in[7];
    const float* b_hh0_b = (const float*)d_in[8];
    const float* w_ih1_f = (const float*)d_in[9];
    const float* w_hh1_f = (const float*)d_in[10];
    const float* b_ih1_f = (const float*)d_in[11];
    const float* b_hh1_f = (const float*)d_in[12];
    const float* w_ih1_b = (const float*)d_in[13];
    const float* w_hh1_b = (const float*)d_in[14];
    const float* b_ih1_b = (const float*)d_in[15];
    const float* b_hh1_b = (const float*)d_in[16];
    float* out = (float*)d_out;

    float *xg_f, *xg_b, *l0;
    __nv_bfloat16 *a_hi, *a_lo, *whi_f, *wlo_f, *whi_b, *wlo_b;
    cudaGetSymbolAddress((void**)&xg_f,  g_xg_f);
    cudaGetSymbolAddress((void**)&xg_b,  g_xg_b);
    cudaGetSymbolAddress((void**)&l0,    g_l0);
    cudaGetSymbolAddress((void**)&a_hi,  g_a_hi);
    cudaGetSymbolAddress((void**)&a_lo,  g_a_lo);
    cudaGetSymbolAddress((void**)&whi_f, g_whi_f);
    cudaGetSymbolAddress((void**)&wlo_f, g_wlo_f);
    cudaGetSymbolAddress((void**)&whi_b, g_whi_b);
    cudaGetSymbolAddress((void**)&wlo_b, g_wlo_b);

    cudaFuncSetAttribute(lstm_persist_mma,
                         cudaFuncAttributeMaxDynamicSharedMemorySize, RSMEM_BYTES);

    const dim3 gemm_grid(G4 / 128, MROWS / 128);   // (16, 256)

    // ---- layer 0: split + mma GEMMs (K=512) ----
    split_bf16<<<512, 256>>>(x,       a_hi,  a_lo,  (size_t)MROWS * 512);
    split_bf16<<<256, 256>>>(w_ih0_f, whi_f, wlo_f, (size_t)G4 * 512);
    split_bf16<<<256, 256>>>(w_ih0_b, whi_b, wlo_b, (size_t)G4 * 512);
    gemm_mma<<<gemm_grid, 256>>>(a_hi, a_lo, whi_f, wlo_f, b_ih0_f, b_hh0_f, xg_f, 512);
    gemm_mma<<<gemm_grid, 256>>>(a_hi, a_lo, whi_b, wlo_b, b_ih0_b, b_hh0_b, xg_b, 512);
    init_state<<<256, 256>>>();
    // layer-0 recurrence writes a_hi/a_lo (next layer's A operand) directly
    lstm_persist_mma<<<NBLK, 512, RSMEM_BYTES>>>(xg_f, xg_b, w_hh0_f, w_hh0_b,
                                                 l0, a_hi, a_lo);

    // ---- layer 1: weight splits + mma GEMMs (K=1024) ----
    split_bf16<<<256, 256>>>(w_ih1_f, whi_f, wlo_f, (size_t)G4 * 1024);
    split_bf16<<<256, 256>>>(w_ih1_b, whi_b, wlo_b, (size_t)G4 * 1024);
    gemm_mma<<<gemm_grid, 256>>>(a_hi, a_lo, whi_f, wlo_f, b_ih1_f, b_hh1_f, xg_f, 1024);
    gemm_mma<<<gemm_grid, 256>>>(a_hi, a_lo, whi_b, wlo_b, b_ih1_b, b_hh1_b, xg_b, 1024);
    init_state<<<256, 256>>>();
    lstm_persist_mma<<<NBLK, 512, RSMEM_BYTES>>>(xg_f, xg_b, w_hh1_f, w_hh1_b,
                                                 out, nullptr, nullptr);
}

// round 17
// speedup vs baseline: 1.6255x; 1.1014x over previous
#include <cuda_runtime.h>
#include <cuda_bf16.h>
#include <cuda_fp16.h>
#include <cstdint>
#include <math.h>

// LSTM_38646115729591 — 2-layer bidirectional LSTM.
// T=512, B=64, D=512, H=512. Output [T,B,2H] fp32.
// Input GEMMs: mma.sync bf16, 2-term weight split (A bf16, W = Whi+Wlo),
//              double-buffered cp.async.
// Recurrence: persistent mma.sync fp16; round-12 simple barrier.

#define T_LEN 512
#define BATCH 64
#define HID   512
#define G4    2048
#define MROWS (T_LEN * BATCH)   // 32768
#define NBLK  128

// recurrence smem layout (bytes)
#define OFF_W   0                 // 32 rows x 512 fp16 = 32768
#define OFF_H   32768             // 64 rows x 512 fp16 = 65536
#define OFF_PSM 98304             // 3 * 8192 reduction scratch
#define RSMEM_BYTES (98304 + 24576)   // 122880

typedef unsigned long long ull;

// ---- static device scratch ----
__device__ float g_xg_f[(size_t)MROWS * G4];
__device__ float g_xg_b[(size_t)MROWS * G4];
__device__ float g_l0[(size_t)MROWS * 2 * HID];
__device__ __half g_hfp[2][2][BATCH * HID];     // [dir][ping] fp16 h

// barrier state — round-12 layout (simple, unpadded; fastest measured)
__device__ unsigned g_cnt_leaf[2][4];
__device__ unsigned g_cnt_root[2];
__device__ unsigned g_gen[2];

__device__ __nv_bfloat16 g_a_bf[(size_t)MROWS * 1024];   // A operand (bf16)
__device__ __nv_bfloat16 g_whi_f[(size_t)G4 * 1024];
__device__ __nv_bfloat16 g_wlo_f[(size_t)G4 * 1024];
__device__ __nv_bfloat16 g_whi_b[(size_t)G4 * 1024];
__device__ __nv_bfloat16 g_wlo_b[(size_t)G4 * 1024];

__device__ __forceinline__ float sigf(float x) { return 1.0f / (1.0f + __expf(-x)); }

// ---- scoped sync primitives ----
__device__ __forceinline__ unsigned atom_add_acqrel(unsigned* p, unsigned v) {
    unsigned old;
    asm volatile("atom.add.acq_rel.gpu.u32 %0, [%1], %2;"
                 : "=r"(old) : "l"(p), "r"(v) : "memory");
    return old;
}
__device__ __forceinline__ unsigned ld_acq(const unsigned* p) {
    unsigned v;
    asm volatile("ld.acquire.gpu.u32 %0, [%1];" : "=r"(v) : "l"(p) : "memory");
    return v;
}
__device__ __forceinline__ void st_rel(unsigned* p, unsigned v) {
    asm volatile("st.release.gpu.u32 [%0], %1;" :: "l"(p), "r"(v) : "memory");
}
__device__ __forceinline__ void st_rlx(unsigned* p, unsigned v) {
    asm volatile("st.relaxed.gpu.u32 [%0], %1;" :: "l"(p), "r"(v) : "memory");
}

// ---- mma.sync / cp.async helpers (sm_80 PTX — valid on compute_103) ----
__device__ __forceinline__ uint32_t s2u(const void* p) {
    return (uint32_t)__cvta_generic_to_shared(p);
}
__device__ __forceinline__ void ldsm4(uint32_t* r, uint32_t addr) {
    asm volatile(
        "ldmatrix.sync.aligned.m8n8.x4.shared.b16 {%0,%1,%2,%3}, [%4];"
        : "=r"(r[0]), "=r"(r[1]), "=r"(r[2]), "=r"(r[3]) : "r"(addr));
}
__device__ __forceinline__ void mma_bf16(float* d, const uint32_t* a,
                                         const uint32_t* b) {
    asm volatile(
        "mma.sync.aligned.m16n8k16.row.col.f32.bf16.bf16.f32 "
        "{%0,%1,%2,%3}, {%4,%5,%6,%7}, {%8,%9}, {%0,%1,%2,%3};"
        : "+f"(d[0]), "+f"(d[1]), "+f"(d[2]), "+f"(d[3])
        : "r"(a[0]), "r"(a[1]), "r"(a[2]), "r"(a[3]), "r"(b[0]), "r"(b[1]));
}
__device__ __forceinline__ void mma_f16(float* d, const uint32_t* a,
                                        const uint32_t* b) {
    asm volatile(
        "mma.sync.aligned.m16n8k16.row.col.f32.f16.f16.f32 "
        "{%0,%1,%2,%3}, {%4,%5,%6,%7}, {%8,%9}, {%0,%1,%2,%3};"
        : "+f"(d[0]), "+f"(d[1]), "+f"(d[2]), "+f"(d[3])
        : "r"(a[0]), "r"(a[1]), "r"(a[2]), "r"(a[3]), "r"(b[0]), "r"(b[1]));
}
__device__ __forceinline__ void cpa16(uint32_t smem_dst, const void* gsrc) {
    asm volatile("cp.async.cg.shared.global [%0], [%1], 16;"
                 :: "r"(smem_dst), "l"(__cvta_generic_to_global(gsrc))
                 : "memory");
}
__device__ __forceinline__ void cpa_commit() {
    asm volatile("cp.async.commit_group;" ::: "memory");
}
template <int N>
__device__ __forceinline__ void cpa_wait() {
    asm volatile("cp.async.wait_group %0;" :: "n"(N) : "memory");
}
// split two floats into packed bf16 hi-pair and lo-pair (residual)
__device__ __forceinline__ void split2(float a, float b,
                                       unsigned& h, unsigned& l) {
    const __nv_bfloat16 ha = __float2bfloat16_rn(a);
    const __nv_bfloat16 hb = __float2bfloat16_rn(b);
    const float ra = a - __bfloat162float(ha);
    const float rb = b - __bfloat162float(hb);
    h = (unsigned)__bfloat16_as_ushort(ha)
      | ((unsigned)__bfloat16_as_ushort(hb) << 16);
    l = (unsigned)__bfloat16_as_ushort(__float2bfloat16_rn(ra))
      | ((unsigned)__bfloat16_as_ushort(__float2bfloat16_rn(rb)) << 16);
}
__device__ __forceinline__ unsigned packh2(float a, float b) {
    const __half2 h2 = __floats2half2_rn(a, b);
    return *(const unsigned*)&h2;
}
__device__ __forceinline__ unsigned packb2(float a, float b) {
    return (unsigned)__bfloat16_as_ushort(__float2bfloat16_rn(a))
         | ((unsigned)__bfloat16_as_ushort(__float2bfloat16_rn(b)) << 16);
}

// =====================================================================
// split_bf16: v -> hi = bf16(v), lo = bf16(v - hi)    (weights only)
// =====================================================================
__global__ void split_bf16(const float* __restrict__ src,
                           __nv_bfloat16* __restrict__ hi,
                           __nv_bfloat16* __restrict__ lo,
                           size_t n)
{
    size_t i = (size_t)blockIdx.x * blockDim.x + threadIdx.x;
    const size_t stride = (size_t)gridDim.x * blockDim.x;
    for (; i < n; i += stride) {
        const float v = src[i];
        const __nv_bfloat16 h = __float2bfloat16_rn(v);
        const float r = v - __bfloat162float(h);
        hi[i] = h;
        lo[i] = __float2bfloat16_rn(r);
    }
}

// =====================================================================
// cvt_bf16: plain fp32 -> bf16 convert (activations)
// =====================================================================
__global__ void cvt_bf16(const float* __restrict__ src,
                         __nv_bfloat16* __restrict__ dst, size_t n)
{
    size_t i = (size_t)blockIdx.x * blockDim.x + threadIdx.x;
    const size_t stride = (size_t)gridDim.x * blockDim.x;
    for (; i < n; i += stride)
        dst[i] = __float2bfloat16_rn(src[i]);
}

// =====================================================================
// gemm_mma: C[M,2048] = A[M,K] @ (Whi+Wlo)[2048,K]^T + b1 + b2
// A plain bf16; 2 mma passes (A*Whi + A*Wlo). 2-stage cp.async pipeline.
// CTA 128x128, BK=32; 8 warps = 2(m) x 4(n).
// =====================================================================
__global__ __launch_bounds__(256, 2)
void gemm_mma(const __nv_bfloat16* __restrict__ A,
              const __nv_bfloat16* __restrict__ Whi,
              const __nv_bfloat16* __restrict__ Wlo,
              const float* __restrict__ b1, const float* __restrict__ b2,
              float* __restrict__ C, int K)
{
    __shared__ alignas(128) char sT[2][3][8192];   // [stage][A, Whi, Wlo]
    __shared__ float bias_sm[128];

    const int tid  = threadIdx.x;
    const int wid  = tid >> 5;
    const int lane = tid & 31;
    const int bm   = blockIdx.y * 128;
    const int bn   = blockIdx.x * 128;
    const int wm   = wid & 1;
    const int wn   = wid >> 1;

    if (tid < 128) bias_sm[tid] = b1[bn + tid] + b2[bn + tid];

    const int q   = lane >> 3;
    const int rA  = (q & 1) * 8 + (lane & 7);
    const int caA = q >> 1;
    const int sa  = (rA >> 1) & 3;
    const int rB  = (q >> 1) * 8 + (lane & 7);
    const int cbB = q & 1;
    const int sb  = (rB >> 1) & 3;

    const uint32_t smem0 = s2u(sT);
    const uint32_t aRowB = (uint32_t)(wm * 64 + rA) * 64;
    const uint32_t bRowB = (uint32_t)(wn * 32 + rB) * 64;
    uint32_t aCk[2], bCk[2];
#pragma unroll
    for (int k = 0; k < 2; k++) {
        aCk[k] = (uint32_t)((((k << 1) + caA) ^ sa) * 16);
        bCk[k] = (uint32_t)((((k << 1) + cbB) ^ sb) * 16);
    }

    const int lrow = tid >> 2;
    const int lch  = tid & 3;
    uint32_t stOff[2];
#pragma unroll
    for (int r = 0; r < 2; r++) {
        const int row = lrow + r * 64;
        stOff[r] = (uint32_t)(row * 64 + ((lch ^ ((row >> 1) & 3)) * 16));
    }
    const __nv_bfloat16* src[3][2];
#pragma unroll
    for (int r = 0; r < 2; r++) {
        src[0][r] = A   + (size_t)(bm + lrow + 64 * r) * K + lch * 8;
        src[1][r] = Whi + (size_t)(bn + lrow + 64 * r) * K + lch * 8;
        src[2][r] = Wlo + (size_t)(bn + lrow + 64 * r) * K + lch * 8;
    }

    float acc[4][4][4];
#pragma unroll
    for (int i = 0; i < 4; i++)
#pragma unroll
        for (int j = 0; j < 4; j++)
#pragma unroll
            for (int e = 0; e < 4; e++) acc[i][j][e] = 0.0f;

    const int nslab = K / 32;

    // prologue: stage 0
#pragma unroll
    for (int t = 0; t < 3; t++)
#pragma unroll
        for (int r = 0; r < 2; r++)
            cpa16(s2u(sT[0][t]) + stOff[r], src[t][r]);
    cpa_commit();

    for (int s = 0; s < nslab; s++) {
        const int cur = s & 1;
        if (s + 1 < nslab) {
#pragma unroll
            for (int t = 0; t < 3; t++)
#pragma unroll
                for (int r = 0; r < 2; r++)
                    cpa16(s2u(sT[cur ^ 1][t]) + stOff[r],
                          src[t][r] + (s + 1) * 32);
            cpa_commit();
            cpa_wait<1>();
        } else {
            cpa_wait<0>();
        }
        __syncthreads();

        const uint32_t base = smem0 + (uint32_t)cur * 24576u;
#pragma unroll
        for (int kx = 0; kx < 2; kx++) {
            uint32_t ah[16], wh[8], wl[8];
#pragma unroll
            for (int fm = 0; fm < 4; fm++)
                ldsm4(&ah[fm * 4], base + 0 * 8192 + aRowB + fm * 1024 + aCk[kx]);
#pragma unroll
            for (int fp = 0; fp < 2; fp++)
                ldsm4(&wh[fp * 4], base + 1 * 8192 + bRowB + fp * 1024 + bCk[kx]);
#pragma unroll
            for (int fm = 0; fm < 4; fm++)
#pragma unroll
                for (int fn = 0; fn < 4; fn++)
                    mma_bf16(acc[fm][fn], &ah[fm * 4], &wh[fn * 2]);
#pragma unroll
            for (int fp = 0; fp < 2; fp++)
                ldsm4(&wl[fp * 4], base + 2 * 8192 + bRowB + fp * 1024 + bCk[kx]);
#pragma unroll
            for (int fm = 0; fm < 4; fm++)
#pragma unroll
                for (int fn = 0; fn < 4; fn++)
                    mma_bf16(acc[fm][fn], &ah[fm * 4], &wl[fn * 2]);
        }
        __syncthreads();   // stage reuse guard
    }

#pragma unroll
    for (int fm = 0; fm < 4; fm++) {
        const int m0 = bm + wm * 64 + fm * 16 + (lane >> 2);
#pragma unroll
        for (int fn = 0; fn < 4; fn++) {
            const int c0 = wn * 32 + fn * 8 + (lane & 3) * 2;
            float2 v0, v1;
            v0.x = acc[fm][fn][0] + bias_sm[c0];
            v0.y = acc[fm][fn][1] + bias_sm[c0 + 1];
            v1.x = acc[fm][fn][2] + bias_sm[c0];
            v1.y = acc[fm][fn][3] + bias_sm[c0 + 1];
            *(float2*)&C[(size_t)m0 * G4 + bn + c0] = v0;
            *(float2*)&C[(size_t)(m0 + 8) * G4 + bn + c0] = v1;
        }
    }
}

// =====================================================================
// init_state: zero fp16 h ping-pong planes + barrier state
// =====================================================================
__global__ void init_state()
{
    const int i = blockIdx.x * blockDim.x + threadIdx.x;   // 65536 threads
    unsigned* p = (unsigned*)g_hfp;                        // 65536 words
    p[i] = 0u;
    if (i < 4) { g_cnt_leaf[0][i] = 0u; g_cnt_leaf[1][i] = 0u; }
    if (i < 2) { g_cnt_root[i] = 0u; g_gen[i] = 0u; }
}

// =====================================================================
// Per-direction tree barrier — round-12 version
// =====================================================================
__device__ __forceinline__ void dir_barrier(int dir, int bx)
{
    __syncthreads();
    if (threadIdx.x == 0) {
        unsigned* gen_p = &g_gen[dir];
        const unsigned gen = ld_acq(gen_p);
        const int g = (bx & 63) >> 4;
        if (atom_add_acqrel(&g_cnt_leaf[dir][g], 1u) == 15u) {
            st_rlx(&g_cnt_leaf[dir][g], 0u);
            if (atom_add_acqrel(&g_cnt_root[dir], 1u) == 3u) {
                st_rlx(&g_cnt_root[dir], 0u);
                st_rel(gen_p, gen + 1u);
            } else {
                while (ld_acq(gen_p) == gen) { }
            }
        } else {
            while (ld_acq(gen_p) == gen) { }
        }
    }
    __syncthreads();
}

// =====================================================================
// Persistent recurrence via fp16 mma.sync (round-12/16 structure).
// Layer-0 variant writes bf16 A operand for the next layer's GEMM.
// =====================================================================
__global__ __launch_bounds__(512) void lstm_persist_mma(
    const float* __restrict__ xg_f, const float* __restrict__ xg_b,
    const float* __restrict__ whh_f, const float* __restrict__ whh_b,
    float* __restrict__ out,
    __nv_bfloat16* __restrict__ aB)
{
    extern __shared__ char smc[];
    const uint32_t smem_u = s2u(smc);
    float* psm = (float*)(smc + OFF_PSM);

    const int tid  = threadIdx.x;
    const int bx   = blockIdx.x;
    const int dir  = bx >> 6;
    const int hb   = bx & 63;
    const int u0   = hb * 8;
    const int w    = tid >> 5;
    const int lane = tid & 31;
    const int wm   = w & 3;
    const int kq   = w >> 2;                               // 0..3
    const int q    = lane >> 3;
    const int l7   = lane & 7;

    const float* xg  = dir ? xg_b : xg_f;
    const float* whh = dir ? whh_b : whh_f;

    // ---- one-time: W slice (32 rows x 512) -> smem fp16, swizzled ----
    for (int ci = tid; ci < 32 * 64; ci += 512) {          // 16B chunks
        const int row = ci >> 6, c = ci & 63;
        const int grow = (row >> 3) * HID + u0 + (row & 7);
        const float4 f0 = __ldg((const float4*)&whh[(size_t)grow * HID + c * 8]);
        const float4 f1 = __ldg((const float4*)&whh[(size_t)grow * HID + c * 8 + 4]);
        const uint4 v = make_uint4(packh2(f0.x, f0.y), packh2(f0.z, f0.w),
                                   packh2(f1.x, f1.y), packh2(f1.z, f1.w));
        const uint32_t dst = (uint32_t)(row * 1024 + ((c ^ (row & 7)) << 4));
        *(uint4*)(smc + OFF_W + dst) = v;
    }
    __syncthreads();

    // ldmatrix lane geometry
    const int aRow = wm * 16 + (q & 1) * 8 + l7;           // A rows (batch)
    const int aSel = q >> 1;
    const int aXor = aRow & 7;
    const uint32_t aBase = (uint32_t)aRow * 1024;
    const int bRow = (q >> 1) * 8 + l7;                    // B rows (gates)
    const int bSel = q & 1;
    const int bXor = bRow & 7;
    const uint32_t bBase0 = (uint32_t)bRow * 1024;
    const uint32_t bBase1 = (uint32_t)(bRow + 16) * 1024;

    const int m0 = wm * 16 + (lane >> 2);                  // epilogue cells
    const int j2 = (lane & 3) * 2;
    const int uu2 = u0 + j2;

    float cst[2][2] = {{0.0f, 0.0f}, {0.0f, 0.0f}};        // c-state (kq==0)
    const int kb8 = kq * 8;

    for (int t = 0; t < T_LEN; t++) {
        const int t_eff = dir ? (T_LEN - 1 - t) : t;
        const int ping  = t & 1;
        const __half* hp = &g_hfp[dir][ping][0];
        __half*       hn = &g_hfp[dir][ping ^ 1][0];

        // ---- stage h plane (64 x 512 fp16) via cp.async ----
#pragma unroll
        for (int it = 0; it < 8; it++) {
            const int ci = tid + it * 512;                 // 0..4095
            const int row = ci >> 6, c = ci & 63;
            const uint32_t dst = (uint32_t)(row * 1024 + ((c ^ (row & 7)) << 4));
            cpa16(smem_u + OFF_H + dst, hp + row * 512 + c * 8);
        }

        // prefetch xg gate rows while cp.async is in flight
        float2 xr[4][2];
        if (kq == 0) {
#pragma unroll
            for (int g = 0; g < 4; g++)
#pragma unroll
                for (int r = 0; r < 2; r++) {
                    const int b = m0 + r * 8;
                    xr[g][r] = __ldg((const float2*)
                        &xg[((size_t)t_eff * BATCH + b) * G4 + g * HID + uu2]);
                }
        }

        cpa_commit();
        cpa_wait<0>();
        __syncthreads();

        // ---- mma over this warp's K-quarter: 8 k16 steps ----
        float acc[4][4];
#pragma unroll
        for (int fn = 0; fn < 4; fn++)
#pragma unroll
            for (int e = 0; e < 4; e++) acc[fn][e] = 0.0f;

#pragma unroll
        for (int kk = 0; kk < 8; kk++) {
            const int s = kb8 + kk;
            const uint32_t ca = (uint32_t)(((2 * s + aSel) ^ aXor) << 4);
            const uint32_t cb = (uint32_t)(((2 * s + bSel) ^ bXor) << 4);
            uint32_t a[4], w0[4], w1[4];
            ldsm4(a,  smem_u + OFF_H + aBase + ca);
            ldsm4(w0, smem_u + OFF_W + bBase0 + cb);
            ldsm4(w1, smem_u + OFF_W + bBase1 + cb);
            mma_f16(acc[0], a, w0 + 0);
            mma_f16(acc[1], a, w0 + 2);
            mma_f16(acc[2], a, w1 + 0);
            mma_f16(acc[3], a, w1 + 2);
        }

        // ---- K-quarter reduction (kq 1..3 -> psm; kq 0 finalizes) ----
        if (kq != 0) {
            float* pp = psm + ((kq - 1) * 128 + wm * 32 + lane) * 16;
#pragma unroll
            for (int fn = 0; fn < 4; fn++)
#pragma unroll
                for (int e = 0; e < 4; e++) pp[fn * 4 + e] = acc[fn][e];
        }
        __syncthreads();

        if (kq == 0) {
#pragma unroll
            for (int kqq = 0; kqq < 3; kqq++) {
                const float* pp = psm + (kqq * 128 + wm * 32 + lane) * 16;
#pragma unroll
                for (int fn = 0; fn < 4; fn++)
#pragma unroll
                    for (int e = 0; e < 4; e++) acc[fn][e] += pp[fn * 4 + e];
            }

#pragma unroll
            for (int r = 0; r < 2; r++) {
                const int b = m0 + r * 8;
                float hv[2];
#pragma unroll
                for (int cc = 0; cc < 2; cc++) {
                    const int e = r * 2 + cc;
                    const float gi = acc[0][e] + (cc ? xr[0][r].y : xr[0][r].x);
                    const float gf = acc[1][e] + (cc ? xr[1][r].y : xr[1][r].x);
                    const float gg = acc[2][e] + (cc ? xr[2][r].y : xr[2][r].x);
                    const float go = acc[3][e] + (cc ? xr[3][r].y : xr[3][r].x);
                    cst[r][cc] = sigf(gf) * cst[r][cc] + sigf(gi) * tanhf(gg);
                    hv[cc] = sigf(go) * tanhf(cst[r][cc]);
                }
                __stcg((unsigned*)(hn + b * 512 + uu2), packh2(hv[0], hv[1]));
                if (aB) {
                    // fused next-layer GEMM operand: A[t*64+b, dir*512+u] (bf16)
                    const size_t arow = ((size_t)t_eff * BATCH + b) * 1024
                                        + dir * HID + uu2;
                    __stcg((unsigned*)(aB + arow), packb2(hv[0], hv[1]));
                } else {
                    *(float2*)&out[((size_t)t_eff * BATCH + b) * (2 * HID)
                                   + dir * HID + uu2] = make_float2(hv[0], hv[1]);
                }
            }
        }

        dir_barrier(dir, bx);
    }
}

// =====================================================================
// host
// =====================================================================
extern "C" void kernel_launch(void* const* d_in, const int* in_sizes, int n_in,
                              void* d_out, int out_size)
{
    const float* x       = (const float*)d_in[0];
    const float* w_ih0_f = (const float*)d_in[1];
    const float* w_hh0_f = (const float*)d_in[2];
    const float* b_ih0_f = (const float*)d_in[3];
    const float* b_hh0_f = (const float*)d_in[4];
    const float* w_ih0_b = (const float*)d_in[5];
    const float* w_hh0_b = (const float*)d_in[6];
    const float* b_ih0_b = (const float*)d_in[7];
    const float* b_hh0_b = (const float*)d_in[8];
    const float* w_ih1_f = (const float*)d_in[9];
    const float* w_hh1_f = (const float*)d_in[10];
    const float* b_ih1_f = (const float*)d_in[11];
    const float* b_hh1_f = (const float*)d_in[12];
    const float* w_ih1_b = (const float*)d_in[13];
    const float* w_hh1_b = (const float*)d_in[14];
    const float* b_ih1_b = (const float*)d_in[15];
    const float* b_hh1_b = (const float*)d_in[16];
    float* out = (float*)d_out;

    float *xg_f, *xg_b, *l0;
    __nv_bfloat16 *a_bf, *whi_f, *wlo_f, *whi_b, *wlo_b;
    cudaGetSymbolAddress((void**)&xg_f,  g_xg_f);
    cudaGetSymbolAddress((void**)&xg_b,  g_xg_b);
    cudaGetSymbolAddress((void**)&l0,    g_l0);
    cudaGetSymbolAddress((void**)&a_bf,  g_a_bf);
    cudaGetSymbolAddress((void**)&whi_f, g_whi_f);
    cudaGetSymbolAddress((void**)&wlo_f, g_wlo_f);
    cudaGetSymbolAddress((void**)&whi_b, g_whi_b);
    cudaGetSymbolAddress((void**)&wlo_b, g_wlo_b);

    cudaFuncSetAttribute(lstm_persist_mma,
                         cudaFuncAttributeMaxDynamicSharedMemorySize, RSMEM_BYTES);

    const dim3 gemm_grid(G4 / 128, MROWS / 128);   // (16, 256)

    // ---- layer 0: convert/split + mma GEMMs (K=512) ----
    cvt_bf16<<<512, 256>>>(x, a_bf, (size_t)MROWS * 512);
    split_bf16<<<256, 256>>>(w_ih0_f, whi_f, wlo_f, (size_t)G4 * 512);
    split_bf16<<<256, 256>>>(w_ih0_b, whi_b, wlo_b, (size_t)G4 * 512);
    gemm_mma<<<gemm_grid, 256>>>(a_bf, whi_f, wlo_f, b_ih0_f, b_hh0_f, xg_f, 512);
    gemm_mma<<<gemm_grid, 256>>>(a_bf, whi_b, wlo_b, b_ih0_b, b_hh0_b, xg_b, 512);
    init_state<<<256, 256>>>();
    // layer-0 recurrence writes a_bf (next layer's A operand) directly
    lstm_persist_mma<<<NBLK, 512, RSMEM_BYTES>>>(xg_f, xg_b, w_hh0_f, w_hh0_b,
                                                 l0, a_bf);

    // ---- layer 1: weight splits + mma GEMMs (K=1024) ----
    split_bf16<<<256, 256>>>(w_ih1_f, whi_f, wlo_f, (size_t)G4 * 1024);
    split_bf16<<<256, 256>>>(w_ih1_b, whi_b, wlo_b, (size_t)G4 * 1024);
    gemm_mma<<<gemm_grid, 256>>>(a_bf, whi_f, wlo_f, b_ih1_f, b_hh1_f, xg_f, 1024);
    gemm_mma<<<gemm_grid, 256>>>(a_bf, whi_b, wlo_b, b_ih1_b, b_hh1_b, xg_b, 1024);
    init_state<<<256, 256>>>();
    lstm_persist_mma<<<NBLK, 512, RSMEM_BYTES>>>(xg_f, xg_b, w_hh1_f, w_hh1_b,
                                                 out, nullptr);
}